// round 4
// baseline (speedup 1.0000x reference)
#include <cuda_runtime.h>
#include <math.h>

#define NB 1024
#define EPSV 1e-8f
#define QCAP 65536

struct BP {
    float cx, cy, rad, area;
    float cr, sr, hdx, hdy;
    float zlo, zhi, vol, pad;
    float corx[4];
    float cory[4];
};

__device__ BP g_gtp[NB];
__device__ BP g_prp[NB];
__device__ float4 g_gtc[NB];     // gt (cx,cy,rad,-)
__device__ float4 g_prc[NB];     // pred (cx,cy,rad,-)
__device__ int g_order[NB];
__device__ unsigned g_mask[NB * 32];
__device__ float4 g_keptc[NB];   // kept (cx,cy,rad, orig idx as bits)
__device__ int g_kcount;
__device__ unsigned g_qn[QCAP];  // NMS heavy-pair queue (sorted-space i,j)
__device__ unsigned g_qr[QCAP];  // row heavy-pair queue (row, orig j)
__device__ int g_qn_n;
__device__ int g_qr_n;
__device__ unsigned long long g_best[NB];

__device__ __forceinline__ void fill_bp(BP& p, const float* b, float4* cen) {
    float x = b[0], y = b[1], z = b[2];
    float dx = b[3], dy = b[4], dz = b[5], r = b[6];
    float cr = cosf(r), sr = sinf(r);
    p.cx = x; p.cy = y; p.cr = cr; p.sr = sr;
    p.hdx = 0.5f * dx; p.hdy = 0.5f * dy;
    float rad = sqrtf(p.hdx * p.hdx + p.hdy * p.hdy) + 1e-3f;
    p.rad = rad;
    p.area = dx * dy;
    p.vol = dx * dy * dz;
    p.zlo = z - 0.5f * dz; p.zhi = z + 0.5f * dz;
    const float sx[4] = {0.5f, 0.5f, -0.5f, -0.5f};
    const float sy[4] = {0.5f, -0.5f, -0.5f, 0.5f};
#pragma unroll
    for (int c = 0; c < 4; c++) {
        float lx = sx[c] * dx, ly = sy[c] * dy;
        p.corx[c] = lx * cr - ly * sr + x;
        p.cory[c] = lx * sr + ly * cr + y;
    }
    *cen = make_float4(x, y, rad, 0.0f);
}

// Pseudo-angle: exact order-equivalent to atan2f (same quadrant ordering,
// same signed-zero branch-cut behavior), far cheaper and shorter latency.
__device__ __forceinline__ float pang(float y, float x) {
    float d = fabsf(x) + fabsf(y);
    if (d == 0.0f) return 0.0f;            // atan2(0,0)=0
    return copysignf(1.0f - x / d, y);
}

// Exact replication of reference _rect_inter_area (collection order,
// tolerances, stable angle sort via order-equivalent key, shoelace).
__device__ float inter_area(const BP& A, const BP& B) {
    float px[24], py[24];
    int m = 0;
#pragma unroll
    for (int c = 0; c < 4; c++) {
        float dx = A.corx[c] - B.cx, dy = A.cory[c] - B.cy;
        float lx = dx * B.cr + dy * B.sr;
        float ly = -dx * B.sr + dy * B.cr;
        if (fabsf(lx) <= B.hdx + 1e-5f && fabsf(ly) <= B.hdy + 1e-5f) {
            px[m] = A.corx[c]; py[m] = A.cory[c]; m++;
        }
    }
#pragma unroll
    for (int c = 0; c < 4; c++) {
        float dx = B.corx[c] - A.cx, dy = B.cory[c] - A.cy;
        float lx = dx * A.cr + dy * A.sr;
        float ly = -dx * A.sr + dy * A.cr;
        if (fabsf(lx) <= A.hdx + 1e-5f && fabsf(ly) <= A.hdy + 1e-5f) {
            px[m] = B.corx[c]; py[m] = B.cory[c]; m++;
        }
    }
#pragma unroll
    for (int i = 0; i < 4; i++) {
        int i1 = (i + 1) & 3;
        float a0x = A.corx[i], a0y = A.cory[i];
        float d1x = A.corx[i1] - a0x, d1y = A.cory[i1] - a0y;
#pragma unroll
        for (int j = 0; j < 4; j++) {
            int j1 = (j + 1) & 3;
            float b0x = B.corx[j], b0y = B.cory[j];
            float d2x = B.corx[j1] - b0x, d2y = B.cory[j1] - b0y;
            float r0x = b0x - a0x, r0y = b0y - a0y;
            float den = d1x * d2y - d1y * d2x;
            if (fabsf(den) > EPSV) {
                float t = (r0x * d2y - r0y * d2x) / den;
                float u = (r0x * d1y - r0y * d1x) / den;
                if (t >= 0.f && t <= 1.f && u >= 0.f && u <= 1.f) {
                    px[m] = a0x + t * d1x; py[m] = a0y + t * d1y; m++;
                }
            }
        }
    }
    if (m < 3) return 0.0f;
    float sx = 0.f, sy = 0.f;
    for (int i = 0; i < m; i++) { sx += px[i]; sy += py[i]; }
    float inv = 1.0f / (float)m;
    float ctx = sx * inv, cty = sy * inv;
    float ang[24];
    for (int i = 0; i < m; i++) {
        px[i] -= ctx; py[i] -= cty;
        ang[i] = pang(py[i], px[i]);
    }
    for (int i = 1; i < m; i++) {
        float a = ang[i], x = px[i], y = py[i];
        int j = i - 1;
        while (j >= 0 && ang[j] > a) {
            ang[j + 1] = ang[j]; px[j + 1] = px[j]; py[j + 1] = py[j];
            j--;
        }
        ang[j + 1] = a; px[j + 1] = x; py[j + 1] = y;
    }
    float s = 0.f;
    for (int i = 0; i < m; i++) {
        int k2 = (i + 1 < m) ? i + 1 : 0;
        s += px[i] * py[k2] - py[i] * px[k2];
    }
    return 0.5f * fabsf(s);
}

// ---------- k1: prep + rank + zero mask/best/counters ----------
__global__ void k_prep(const float* __restrict__ labels,
                       const float* __restrict__ pred,
                       const float* __restrict__ gt,
                       const float* __restrict__ cls,
                       float* __restrict__ out) {
    int b = blockIdx.x;
    if (b < 8) {
        __shared__ float ssc[NB];
        for (int j = threadIdx.x; j < NB; j += 128) ssc[j] = labels[j];
        __syncthreads();
        int i = b * 128 + threadIdx.x;
        float si = ssc[i];
        int r = 0;
#pragma unroll 8
        for (int j = 0; j < NB; j++) {
            float sj = ssc[j];
            r += (sj > si) || (sj == si && j < i);
        }
        g_order[r] = i;
    } else if (b < 24) {
        int t = (b - 8) * 128 + threadIdx.x;
        if (t < NB) {
            fill_bp(g_prp[t], pred + t * 7, &g_prc[t]);
            float s = 1.0f / (1.0f + expf(-cls[t]));
            float lb = labels[t];
            out[t] = (s > 0.55f && lb > 0.55f) ? 1.0f : 0.0f;
            out[NB + t] = lb;
        } else {
            int i = t - NB;
            fill_bp(g_gtp[i], gt + i * 8, &g_gtc[i]);
        }
    } else if (b < 32) {
        int base = (b - 24) * 4096 + threadIdx.x;
        for (int w = 0; w < 32; w++) g_mask[base + w * 128] = 0u;
    } else {
        // zero best keys (v=0, j=0) + counters
        for (int i = threadIdx.x; i < NB; i += 128)
            g_best[i] = 0x00000000FFFFFFFFull;
        if (threadIdx.x == 0) { g_qn_n = 0; g_qr_n = 0; }
    }
}

// ---------- k2: NMS pair gen (sorted-space upper triangle circ test) ----------
__global__ void k_ngen() {
    __shared__ float4 sc[NB];
    int tid = threadIdx.x;
    for (int i = tid; i < NB; i += 256) sc[i] = g_gtc[g_order[i]];
    __syncthreads();
    for (int i = blockIdx.x; i < NB - 1; i += gridDim.x) {
        float4 a = sc[i];
        for (int j = i + 1 + tid; j < NB; j += 256) {
            float4 bb = sc[j];
            float dx = a.x - bb.x, dy = a.y - bb.y;
            float rs = a.z + bb.z;
            if (dx * dx + dy * dy <= rs * rs) {
                int p = atomicAdd(&g_qn_n, 1);
                if (p < QCAP) g_qn[p] = ((unsigned)i << 10) | (unsigned)j;
            }
        }
    }
}

// ---------- k3: NMS pair compute (one thread per heavy pair) ----------
__global__ void k_ncomp() {
    int n = min(g_qn_n, QCAP);
    for (int t = blockIdx.x * blockDim.x + threadIdx.x; t < n;
         t += gridDim.x * blockDim.x) {
        unsigned e = g_qn[t];
        int i = (int)(e >> 10), j = (int)(e & 1023u);
        const BP& A = g_gtp[g_order[i]];
        const BP& B = g_gtp[g_order[j]];
        float inter = inter_area(A, B);
        float v = inter / fmaxf(A.area + B.area - inter, EPSV);
        if (v > 0.1f) atomicOr(&g_mask[i * 32 + (j >> 5)], 1u << (j & 31));
    }
}

// ---------- k4: serial greedy resolve + compact kept ----------
__global__ void k_nms() {
    __shared__ unsigned skeep[32];
    __shared__ unsigned char sflag[NB];
    __shared__ int swt[8];
    int tid = threadIdx.x;

    if (tid < 32) {
        const int lane = tid;
        unsigned keepw = 0xFFFFFFFFu;
        unsigned cur[32], nxt[32];
#pragma unroll
        for (int i = 0; i < 32; i++) cur[i] = g_mask[i * 32 + lane];
        for (int b = 0; b < 32; b++) {
            if (b + 1 < 32) {
#pragma unroll
                for (int i = 0; i < 32; i++)
                    nxt[i] = g_mask[((b + 1) * 32 + i) * 32 + lane];
            }
            unsigned orall = 0;
#pragma unroll
            for (int i = 0; i < 32; i++) orall |= cur[i];
            unsigned bal = __ballot_sync(0xffffffffu, orall != 0u);
            if (bal != 0u) {
                unsigned K = __shfl_sync(0xffffffffu, keepw, b);
                if ((bal >> b) & 1u) {
#pragma unroll
                    for (int i = 0; i < 32; i++) {
                        unsigned bc = (unsigned)(((int)(K << (31 - i))) >> 31);
                        K &= ~(cur[i] & bc);
                    }
                }
                unsigned kf = __shfl_sync(0xffffffffu, K, b);
                unsigned sup = 0;
#pragma unroll
                for (int i = 0; i < 32; i++) {
                    unsigned bc = (unsigned)(((int)(kf << (31 - i))) >> 31);
                    sup |= cur[i] & bc;
                }
                keepw &= ~sup;
            }
#pragma unroll
            for (int i = 0; i < 32; i++) cur[i] = nxt[i];
        }
        skeep[lane] = keepw;
    }
    __syncthreads();
#pragma unroll
    for (int qq = 0; qq < 4; qq++) {
        int j = tid * 4 + qq;
        int o = g_order[j];
        sflag[o] = (skeep[j >> 5] >> (j & 31)) & 1u;
    }
    __syncthreads();
    int f0 = sflag[tid * 4 + 0], f1 = sflag[tid * 4 + 1];
    int f2 = sflag[tid * 4 + 2], f3 = sflag[tid * 4 + 3];
    int cnt = f0 + f1 + f2 + f3;
    int lane = tid & 31, wid = tid >> 5;
    int pre = cnt;
#pragma unroll
    for (int s = 1; s < 32; s <<= 1) {
        int v = __shfl_up_sync(0xffffffffu, pre, s);
        if (lane >= s) pre += v;
    }
    if (lane == 31) swt[wid] = pre;
    __syncthreads();
    int base = 0;
    for (int w = 0; w < 8; w++) base += (w < wid) ? swt[w] : 0;
    int pos = base + pre - cnt;
    if (f0) { int ix = tid*4+0; float4 c = g_gtc[ix]; c.w = __int_as_float(ix); g_keptc[pos++] = c; }
    if (f1) { int ix = tid*4+1; float4 c = g_gtc[ix]; c.w = __int_as_float(ix); g_keptc[pos++] = c; }
    if (f2) { int ix = tid*4+2; float4 c = g_gtc[ix]; c.w = __int_as_float(ix); g_keptc[pos++] = c; }
    if (f3) { int ix = tid*4+3; float4 c = g_gtc[ix]; c.w = __int_as_float(ix); g_keptc[pos]   = c; }
    if (tid == 255) g_kcount = base + pre;
}

// ---------- k5: row pair gen (pred x kept circ test) ----------
__global__ void k_rgen() {
    __shared__ float4 skept[NB];
    int tid = threadIdx.x;
    int K = g_kcount;
    for (int i = tid; i < K; i += 256) skept[i] = g_keptc[i];
    __syncthreads();
    for (int r = blockIdx.x; r < NB; r += gridDim.x) {
        float4 a = g_prc[r];
        for (int k = tid; k < K; k += 256) {
            float4 bb = skept[k];
            float dx = a.x - bb.x, dy = a.y - bb.y;
            float rs = a.z + bb.z;
            if (dx * dx + dy * dy <= rs * rs) {
                int p = atomicAdd(&g_qr_n, 1);
                unsigned e = ((unsigned)r << 10) |
                             (unsigned)__float_as_int(bb.w);
                if (p < QCAP) g_qr[p] = e;
            }
        }
    }
}

// ---------- k6: row pair compute (one thread per heavy pair) ----------
__global__ void k_rcomp() {
    int n = min(g_qr_n, QCAP);
    for (int t = blockIdx.x * blockDim.x + threadIdx.x; t < n;
         t += gridDim.x * blockDim.x) {
        unsigned e = g_qr[t];
        int r = (int)(e >> 10), j = (int)(e & 1023u);
        const BP& A = g_prp[r];
        const BP& B = g_gtp[j];
        float inter = inter_area(A, B);
        float oh = fmaxf(fminf(A.zhi, B.zhi) - fmaxf(A.zlo, B.zlo), 0.0f);
        float i3 = inter * oh;
        float v = i3 / fmaxf(A.vol + B.vol - i3, EPSV);
        unsigned long long key =
            ((unsigned long long)__float_as_uint(v) << 32) |
            (unsigned long long)(0xFFFFFFFFu - (unsigned)j);
        atomicMax(&g_best[r], key);
    }
}

// ---------- k7: decode best -> out ----------
__global__ void k_fin(float* __restrict__ out) {
    int i = blockIdx.x * blockDim.x + threadIdx.x;
    if (i >= NB) return;
    unsigned long long key = g_best[i];
    float mo = __uint_as_float((unsigned)(key >> 32));
    int j = (int)(0xFFFFFFFFu - (unsigned)(key & 0xFFFFFFFFull));
    mo = (mo > 0.75f) ? 1.0f : ((mo < 0.25f) ? 0.0f : mo);
    out[2 * NB + i] = mo;
    out[3 * NB + i] = (float)j;
}

extern "C" void kernel_launch(void* const* d_in, const int* in_sizes, int n_in,
                              void* d_out, int out_size) {
    const float* labels = (const float*)d_in[0];
    const float* pred   = (const float*)d_in[1];
    const float* gt     = (const float*)d_in[2];
    const float* cls    = (const float*)d_in[3];
    float* out = (float*)d_out;

    k_prep<<<33, 128>>>(labels, pred, gt, cls, out);
    k_ngen<<<128, 256>>>();
    k_ncomp<<<148, 128>>>();
    k_nms<<<1, 256>>>();
    k_rgen<<<128, 256>>>();
    k_rcomp<<<148, 128>>>();
    k_fin<<<8, 128>>>(out);
}